// round 17
// baseline (speedup 1.0000x reference)
#include <cuda_runtime.h>
#include <cuda_fp16.h>
#include <cstdint>

// ============================================================
// out[b,k,c] = softmax_m( tanh(e[b,m]·W1[k] + d[b,k]·W2[m]) ) · x[b,m,c]
// B=16, N=2048, D=128.
// Flash-style fused attention, mma.sync.m16n8k16 + ldmatrix + cp.async.
// tanh bounds scores in [-1,1] -> no online max rescaling needed.
// R16: anti-phase warp groups with ALL compile-time tile indices.
//   A-warps (wid 0-3): wait chunk j -> QK(j) -> expPV(j)      (R8 body)
//   B-warps (wid 4-7): expPV(j) [S carried] -> wait j+1 -> QK(j+1)
//   One A + one B warp per SMSP => exp/LDS of one hides under QK tensor
//   of the other. Chunk arrival via mbarrier + cp.async.mbarrier.arrive
//   so B waits mid-iteration without __syncthreads.
//   Prep = R15 merged single launch (~6us).
// ============================================================

#define DEVI __device__ __forceinline__

constexpr int B_ = 16, N_ = 2048, D_ = 128, F_ = 256;
constexpr int MT = 256;              // queries per CTA
constexpr int KT = 64;               // keys per chunk
constexpr int NCHUNK = N_ / KT;      // 32

// ---------------- device scratch -------------------------------------------
__device__ __half g_Qf[(size_t)B_ * N_ * F_];   // [b,k,256] = [W1[k] | d[b,k]]
__device__ __half g_Kf[(size_t)B_ * N_ * F_];   // [b,m,256] = [e[b,m] | W2[m]]
__device__ __half g_XT[(size_t)B_ * D_ * N_];   // [b,c,m]   = x[b,m,c]

// ---------------- SMEM layout (bytes), XOR-swizzled, no padding -------------
constexpr int SM_Q   = 0;
constexpr int QSIZE  = MT * 512;                // 131072
constexpr int KSTAGE = KT * 512;                // 32768
constexpr int SM_K   = SM_Q + QSIZE;
constexpr int XSTAGE = D_ * 128;                // 16384
constexpr int SM_X   = SM_K + 2 * KSTAGE;
constexpr int SM_MBAR = SM_X + 2 * XSTAGE;      // 229376
constexpr int SMEM_TOTAL = SM_MBAR + 64;        // 229440 (< 232448 opt-in max)

// ---------------- PTX helpers ----------------------------------------------
DEVI uint32_t smem_u32(const void* p) {
    uint32_t a;
    asm("{ .reg .u64 t; cvta.to.shared.u64 t, %1; cvt.u32.u64 %0, t; }" : "=r"(a) : "l"(p));
    return a;
}
DEVI float ex2f(float x) { float y; asm("ex2.approx.f32 %0,%1;" : "=f"(y) : "f"(x)); return y; }
DEVI float tanhf_hw(float x) { float y; asm("tanh.approx.f32 %0,%1;" : "=f"(y) : "f"(x)); return y; }

DEVI void cp_async16(uint32_t dst, const void* src) {
    asm volatile("cp.async.cg.shared.global [%0], [%1], 16;" :: "r"(dst), "l"(src) : "memory");
}
DEVI void cp_mbar_arrive(uint32_t mb) {
    asm volatile("cp.async.mbarrier.arrive.noinc.shared.b64 [%0];" :: "r"(mb) : "memory");
}
#define MBARRIER_INIT(mb, cnt) \
    asm volatile("mbarrier.init.shared.b64 [%0], %1;" :: "r"((uint32_t)(mb)), "r"((uint32_t)(cnt)) : "memory")
#define MBARRIER_WAIT_PARITY(mb, ph) do {                                          \
    uint32_t _m = (uint32_t)(mb); uint32_t _p = (uint32_t)(ph); uint32_t _d;       \
    asm volatile("{ .reg .pred p; mbarrier.try_wait.parity.acquire.cta.shared::cta.b64 p, [%1], %2;" \
                 " selp.b32 %0,1,0,p; }" : "=r"(_d) : "r"(_m), "r"(_p) : "memory"); \
    if (!_d) {                                                                     \
        asm volatile("{ .reg .pred P1; WL%=: mbarrier.try_wait.parity.acquire.cta.shared::cta.b64 P1, [%0], %1, 0x989680;" \
                     " @P1 bra.uni WD%=; bra.uni WL%=; WD%=: }" :: "r"(_m), "r"(_p) : "memory"); \
    } } while (0)

DEVI void ldsm4(uint32_t r[4], uint32_t addr) {
    asm volatile("ldmatrix.sync.aligned.m8n8.x4.shared.b16 {%0,%1,%2,%3}, [%4];"
                 : "=r"(r[0]), "=r"(r[1]), "=r"(r[2]), "=r"(r[3]) : "r"(addr));
}
DEVI void mma16816(float d[4], const uint32_t a[4], uint32_t b0, uint32_t b1) {
    asm volatile("mma.sync.aligned.m16n8k16.row.col.f32.f16.f16.f32 "
                 "{%0,%1,%2,%3}, {%4,%5,%6,%7}, {%8,%9}, {%0,%1,%2,%3};"
                 : "+f"(d[0]), "+f"(d[1]), "+f"(d[2]), "+f"(d[3])
                 : "r"(a[0]), "r"(a[1]), "r"(a[2]), "r"(a[3]), "r"(b0), "r"(b1));
}

DEVI uint32_t h2_as_u32(__half2 h) { uint32_t u; __builtin_memcpy(&u, &h, 4); return u; }

// w = exp(tanh(s) - 1) = 2^( log2e*(tanh(s) - 1) )   (shift-invariant weight)
DEVI float wfun(float s) {
    const float l2e = 1.4426950409f;
    float t = tanhf_hw(s);
    return ex2f(fmaf(t, l2e, -l2e));
}

// ---------------- merged prep (R15): Qf/Kf build + X transpose --------------
constexpr int QK_WARPS  = B_ * N_ * 2;                    // 65536
constexpr int QK_BLOCKS = QK_WARPS / 8;                   // 8192
constexpr int XT_BLOCKS = (N_ / 32) * (D_ / 32) * B_;     // 4096
constexpr int PREP_BLOCKS = QK_BLOCKS + XT_BLOCKS;        // 12288

__global__ void prep_all(const float* __restrict__ e, const float* __restrict__ d,
                         const float* __restrict__ W1, const float* __restrict__ W2,
                         const float* __restrict__ x) {
    __shared__ float tile[32][33];
    int bid = blockIdx.x;
    if (bid < QK_BLOCKS) {
        int w    = bid * 8 + ((int)threadIdx.x >> 5);
        int lane = threadIdx.x & 31;
        int h = w & 1;
        int k = (w >> 1) & (N_ - 1);
        int b = w >> 12;
        const float4* qsrc;
        const float4* ksrc;
        if (h == 0) {
            qsrc = (const float4*)(W1 + (size_t)k * D_);
            ksrc = (const float4*)(e + ((size_t)(b * N_ + k)) * D_);
        } else {
            qsrc = (const float4*)(d + ((size_t)(b * N_ + k)) * D_);
            ksrc = (const float4*)(W2 + (size_t)k * D_);
        }
        float4 qv = qsrc[lane];
        float4 kv = ksrc[lane];
        uint2 qo = make_uint2(h2_as_u32(__floats2half2_rn(qv.x, qv.y)),
                              h2_as_u32(__floats2half2_rn(qv.z, qv.w)));
        uint2 ko = make_uint2(h2_as_u32(__floats2half2_rn(kv.x, kv.y)),
                              h2_as_u32(__floats2half2_rn(kv.z, kv.w)));
        size_t roff = ((size_t)(b * N_ + k)) * F_ + h * 128 + lane * 4;
        *(uint2*)(g_Qf + roff) = qo;
        *(uint2*)(g_Kf + roff) = ko;
    } else {
        int bid2 = bid - QK_BLOCKS;
        int m0 = (bid2 & 63) * 32;
        int c0 = ((bid2 >> 6) & 3) * 32;
        int b  = bid2 >> 8;
        int tx = threadIdx.x & 31, ty = (int)threadIdx.x >> 5;
#pragma unroll
        for (int i = 0; i < 4; i++)
            tile[ty + 8 * i][tx] = x[((size_t)(b * N_ + m0 + ty + 8 * i)) * D_ + c0 + tx];
        __syncthreads();
        int mp = tx & 15;
        int hi = tx >> 4;
#pragma unroll
        for (int i = 0; i < 2; i++) {
            int c = i * 16 + ty * 2 + hi;
            uint32_t v = h2_as_u32(__floats2half2_rn(tile[2 * mp][c], tile[2 * mp + 1][c]));
            *(uint32_t*)(g_XT + ((size_t)(b * D_ + c0 + c)) * N_ + m0 + 2 * mp) = v;
        }
    }
}

// ---------------- chunk loader (no commit groups; mbarrier-tracked) ---------
DEVI void load_chunk(int b, int m0, int stage, uint32_t sb, int tid) {
    const uint32_t stK = sb + SM_K + stage * KSTAGE;
    const uint32_t stX = sb + SM_X + stage * XSTAGE;
    const __half* kbase = g_Kf + ((size_t)(b * N_ + m0)) * F_;
#pragma unroll
    for (int i = 0; i < 8; i++) {
        int lin = tid + i * 256;          // 0..2047
        int row = lin >> 5;               // 0..63
        int ch  = lin & 31;
        cp_async16(stK + row * 512 + ((ch ^ (row & 7)) << 4),
                   kbase + (size_t)row * F_ + ch * 8);
    }
    const __half* xbase = g_XT + (size_t)b * D_ * N_ + m0;
#pragma unroll
    for (int i = 0; i < 4; i++) {
        int lin = tid + i * 256;          // 0..1023
        int row = lin >> 3;               // c: 0..127
        int ch  = lin & 7;
        cp_async16(stX + row * 128 + ((ch ^ (row & 7)) << 4),
                   xbase + (size_t)row * N_ + ch * 8);
    }
}

// ---------------- compute bodies (compile-time indices) ---------------------
DEVI void qk_full(float S[2][8][4], uint32_t krow, uint32_t qrow0, uint32_t qrow1,
                  int ahi, int bhi, int xl) {
#pragma unroll
    for (int t = 0; t < 2; t++)
#pragma unroll
        for (int i = 0; i < 8; i++) { S[t][i][0] = S[t][i][1] = S[t][i][2] = S[t][i][3] = 0.f; }
#pragma unroll
    for (int kt = 0; kt < 16; kt++) {
        const uint32_t cswA = (uint32_t)(((kt * 2 + ahi) ^ xl) << 4);
        const uint32_t cswB = (uint32_t)(((kt * 2 + bhi) ^ xl) << 4);
        uint32_t qa0[4], qa1[4];
        ldsm4(qa0, qrow0 + cswA);
        ldsm4(qa1, qrow1 + cswA);
#pragma unroll
        for (int ng = 0; ng < 4; ng++) {
            uint32_t kb[4];
            ldsm4(kb, krow + ng * 16 * 512 + cswB);
            mma16816(S[0][2 * ng],     qa0, kb[0], kb[1]);
            mma16816(S[0][2 * ng + 1], qa0, kb[2], kb[3]);
            mma16816(S[1][2 * ng],     qa1, kb[0], kb[1]);
            mma16816(S[1][2 * ng + 1], qa1, kb[2], kb[3]);
        }
    }
}

DEVI void exppv_full(const float S[2][8][4], uint32_t xrow,
                     float O[2][16][4], float den[2][2], int bhi, int xl) {
#pragma unroll
    for (int t2 = 0; t2 < 4; t2++) {
        uint32_t Pf[2][4];
#pragma unroll
        for (int t = 0; t < 2; t++) {
            int j0 = 2 * t2, j1 = 2 * t2 + 1;
            __half2 h00 = __floats2half2_rn(wfun(S[t][j0][0]), wfun(S[t][j0][1]));
            __half2 h01 = __floats2half2_rn(wfun(S[t][j0][2]), wfun(S[t][j0][3]));
            __half2 h10 = __floats2half2_rn(wfun(S[t][j1][0]), wfun(S[t][j1][1]));
            __half2 h11 = __floats2half2_rn(wfun(S[t][j1][2]), wfun(S[t][j1][3]));
            float2 f;
            f = __half22float2(h00); den[t][0] += f.x + f.y;
            f = __half22float2(h01); den[t][1] += f.x + f.y;
            f = __half22float2(h10); den[t][0] += f.x + f.y;
            f = __half22float2(h11); den[t][1] += f.x + f.y;
            Pf[t][0] = h2_as_u32(h00);   // a0: row g,   k 0-7
            Pf[t][1] = h2_as_u32(h01);   // a1: row g+8, k 0-7
            Pf[t][2] = h2_as_u32(h10);   // a2: row g,   k 8-15
            Pf[t][3] = h2_as_u32(h11);   // a3: row g+8, k 8-15
        }
        const uint32_t cswB = (uint32_t)(((t2 * 2 + bhi) ^ xl) << 4);
#pragma unroll
        for (int cc = 0; cc < 8; cc++) {
            uint32_t xb[4];
            ldsm4(xb, xrow + cc * 16 * 128 + cswB);
            mma16816(O[0][2 * cc],     Pf[0], xb[0], xb[1]);
            mma16816(O[0][2 * cc + 1], Pf[0], xb[2], xb[3]);
            mma16816(O[1][2 * cc],     Pf[1], xb[0], xb[1]);
            mma16816(O[1][2 * cc + 1], Pf[1], xb[2], xb[3]);
        }
    }
}

// ---------------- main fused attention kernel -------------------------------
__global__ void __launch_bounds__(256, 1) attn_kernel(float* __restrict__ out) {
    extern __shared__ __align__(1024) char smem[];
    const uint32_t sb = smem_u32(smem);
    const int tid = threadIdx.x;
    const int wid = tid >> 5;
    const int lane = tid & 31;
    const int b = blockIdx.y;
    const int k0 = blockIdx.x * MT;
    const int qb = wid * 32;             // this warp's 32 query rows (2 m-tiles)
    const int grp = wid >> 2;            // 0: A-warps, 1: B-warps (SMSP = wid%4)
    const uint32_t mb0 = sb + SM_MBAR;
    const uint32_t mb1 = sb + SM_MBAR + 8;

    if (tid == 0) { MBARRIER_INIT(mb0, 256); MBARRIER_INIT(mb1, 256); }
    __syncthreads();

    // ---- issue Q + chunk0 (arrive mb0 covers Q too) + chunk1 ----
    {
        const __half* qbase = g_Qf + ((size_t)(b * N_ + k0)) * F_;
#pragma unroll
        for (int i = 0; i < 32; i++) {
            int lin = tid + i * 256;      // 0..8191
            int row = lin >> 5;           // 0..255
            int ch  = lin & 31;
            cp_async16(sb + SM_Q + row * 512 + ((ch ^ (row & 7)) << 4),
                       qbase + (size_t)row * F_ + ch * 8);
        }
    }
    load_chunk(b, 0, 0, sb, tid);
    cp_mbar_arrive(mb0);
    load_chunk(b, KT, 1, sb, tid);
    cp_mbar_arrive(mb1);

    float O[2][16][4];
#pragma unroll
    for (int t = 0; t < 2; t++)
#pragma unroll
        for (int i = 0; i < 16; i++) { O[t][i][0] = O[t][i][1] = O[t][i][2] = O[t][i][3] = 0.f; }
    float den[2][2] = {{0.f, 0.f}, {0.f, 0.f}};
    float S[2][8][4];

    // ldmatrix lane maps (verified R7+).
    const int arow = lane & 15;
    const int ahi  = lane >> 4;
    const int brow = (lane & 7) + ((lane >> 4) << 3);
    const int bhi  = (lane >> 3) & 1;
    const int xl   = lane & 7;
    const uint32_t qrow0 = sb + SM_Q + (qb + arow) * 512;
    const uint32_t qrow1 = qrow0 + 16 * 512;

    // ---- B prologue: S = QK(chunk 0) ----
    if (grp == 1) {
        MBARRIER_WAIT_PARITY(mb0, 0);
        qk_full(S, sb + SM_K + brow * 512, qrow0, qrow1, ahi, bhi, xl);
    }

    for (int j = 0; j < NCHUNK; j++) {
        const uint32_t stK = sb + SM_K + (j & 1) * KSTAGE;
        const uint32_t stX = sb + SM_X + (j & 1) * XSTAGE;

        if (grp == 0) {
            // A: wait chunk j -> QK(j) -> expPV(j)
            MBARRIER_WAIT_PARITY(mb0 + ((uint32_t)(j & 1) << 3), (j >> 1) & 1);
            qk_full(S, stK + brow * 512, qrow0, qrow1, ahi, bhi, xl);
            exppv_full(S, stX + brow * 128, O, den, bhi, xl);
        } else {
            // B: expPV(j) with carried S -> wait chunk j+1 -> QK(j+1)
            exppv_full(S, stX + brow * 128, O, den, bhi, xl);
            if (j + 1 < NCHUNK) {
                MBARRIER_WAIT_PARITY(mb0 + ((uint32_t)((j + 1) & 1) << 3), ((j + 1) >> 1) & 1);
                const uint32_t stKn = sb + SM_K + ((j + 1) & 1) * KSTAGE;
                qk_full(S, stKn + brow * 512, qrow0, qrow1, ahi, bhi, xl);
            }
        }

        __syncthreads();                  // stage (j&1) fully consumed by all warps
        if (j + 2 < NCHUNK) {
            load_chunk(b, (j + 2) * KT, j & 1, sb, tid);
            cp_mbar_arrive(mb0 + ((uint32_t)(j & 1) << 3));
        }
    }

    // ---- epilogue: quad-reduce denom, scale, store ----
#pragma unroll
    for (int t = 0; t < 2; t++) {
        float d0 = den[t][0], d1 = den[t][1];
        d0 += __shfl_xor_sync(0xffffffffu, d0, 1);
        d0 += __shfl_xor_sync(0xffffffffu, d0, 2);
        d1 += __shfl_xor_sync(0xffffffffu, d1, 1);
        d1 += __shfl_xor_sync(0xffffffffu, d1, 2);
        float inv0 = 1.0f / d0, inv1 = 1.0f / d1;

        int r0 = k0 + qb + t * 16 + (lane >> 2);
        int r1 = r0 + 8;
        float* o0 = out + ((size_t)(b * N_ + r0)) * D_ + (lane & 3) * 2;
        float* o1 = out + ((size_t)(b * N_ + r1)) * D_ + (lane & 3) * 2;
#pragma unroll
        for (int nt = 0; nt < 16; nt++) {
            *(float2*)(o0 + nt * 8) = make_float2(O[t][nt][0] * inv0, O[t][nt][1] * inv0);
            *(float2*)(o1 + nt * 8) = make_float2(O[t][nt][2] * inv1, O[t][nt][3] * inv1);
        }
    }
}

// ---------------- launch ----------------------------------------------------
extern "C" void kernel_launch(void* const* d_in, const int* in_sizes, int n_in,
                              void* d_out, int out_size) {
    const float* x  = (const float*)d_in[0];
    const float* e  = (const float*)d_in[1];
    const float* d  = (const float*)d_in[2];
    const float* W1 = (const float*)d_in[3];
    const float* W2 = (const float*)d_in[4];
    float* out = (float*)d_out;

    cudaFuncSetAttribute(attn_kernel, cudaFuncAttributeMaxDynamicSharedMemorySize, SMEM_TOTAL);

    prep_all<<<PREP_BLOCKS, 256>>>(e, d, W1, W2, x);

    attn_kernel<<<dim3(N_ / MT, B_), 256, SMEM_TOTAL>>>(out);
}